// round 1
// baseline (speedup 1.0000x reference)
#include <cuda_runtime.h>

#define NN   50000
#define EE   800000
#define CIN  32
#define COUT 32
#define KEXP 4

// Order-preserving float atomic max: ints compare like floats for >=0,
// unsigned-min compares like float-max for negatives. Paths are mutually
// consistent on the same address (positive int bits < any negative pattern
// as uint; negative float bits as int < any positive).
__device__ __forceinline__ void atomicMaxFloat(float* addr, float v) {
    if (v >= 0.0f) atomicMax((int*)addr, __float_as_int(v));
    else           atomicMin((unsigned int*)addr, __float_as_uint(v));
}

__global__ void init_kernel(float* __restrict__ out) {
    int i = blockIdx.x * blockDim.x + threadIdx.x;
    const float NEG_INF = __int_as_float(0xff800000);
    int n4 = NN * COUT / 4;
    if (i < n4) {
        ((float4*)out)[i] = make_float4(NEG_INF, NEG_INF, NEG_INF, NEG_INF);
    }
}

// Warp-per-edge, grid-stride. Expert weights (4x32x32 = 16KB) staged in SMEM
// once per block. Lane c computes output channel c; x_j broadcast via shfl.
__global__ __launch_bounds__(512) void edge_kernel(
    const float* __restrict__ x, const float* __restrict__ pos,
    const int*   __restrict__ edge_index,
    const float* __restrict__ ew, const float* __restrict__ gw,
    const float* __restrict__ gb, float* __restrict__ out)
{
    __shared__ float sW[KEXP * CIN * COUT];
    int tid = threadIdx.x;
    for (int i = tid; i < (KEXP * CIN * COUT) / 4; i += blockDim.x)
        ((float4*)sW)[i] = ((const float4*)ew)[i];

    // Gate params into registers (12 floats, uniform, L1-cached)
    float g0x = gw[0], g0y = gw[1], g1x = gw[2], g1y = gw[3];
    float g2x = gw[4], g2y = gw[5], g3x = gw[6], g3y = gw[7];
    float b0 = gb[0], b1 = gb[1], b2 = gb[2], b3 = gb[3];
    __syncthreads();

    int lane   = tid & 31;
    int nwarps = (gridDim.x * blockDim.x) >> 5;
    int w0     = (blockIdx.x * blockDim.x + tid) >> 5;

    for (int e = w0; e < EE; e += nwarps) {
        int2 ei = ((const int2*)edge_index)[e];
        int dst = ei.x, src = ei.y;

        float dx = pos[src * 3]     - pos[dst * 3];
        float dy = pos[src * 3 + 1] - pos[dst * 3 + 1];

        // gate logits + argmax (ties -> lowest index, matching top_k)
        float l0 = fmaf(dx, g0x, fmaf(dy, g0y, b0));
        float l1 = fmaf(dx, g1x, fmaf(dy, g1y, b1));
        float l2 = fmaf(dx, g2x, fmaf(dy, g2y, b2));
        float l3 = fmaf(dx, g3x, fmaf(dy, g3y, b3));
        int bk = 0; float best = l0;
        if (l1 > best) { best = l1; bk = 1; }
        if (l2 > best) { best = l2; bk = 2; }
        if (l3 > best) { best = l3; bk = 3; }

        const float* W = &sW[bk * (CIN * COUT)];
        float xj  = x[src * CIN + lane];   // coalesced 128B, L2-resident
        float acc = 0.0f;
        #pragma unroll
        for (int i = 0; i < CIN; i++) {
            float xv = __shfl_sync(0xffffffffu, xj, i);
            acc = fmaf(xv, W[i * COUT + lane], acc);  // lane-contiguous, no conflicts
        }
        atomicMaxFloat(&out[dst * COUT + lane], acc);
    }
}

// Warp-per-node MLP, in place on out: h -> relu(h@w1^T)@w2^T + h.
// w1/w2 staged transposed in SMEM so per-lane reads are lane-contiguous.
__global__ __launch_bounds__(512) void mlp_kernel(
    const float* __restrict__ w1, const float* __restrict__ w2,
    float* __restrict__ out)
{
    __shared__ float s1t[CIN * 64];    // s1t[i*64 + j] = w1[j][i]
    __shared__ float s2t[64 * COUT];   // s2t[j*32 + c] = w2[c][j]
    int tid = threadIdx.x;
    for (int idx = tid; idx < 64 * CIN; idx += blockDim.x) {
        int j = idx / CIN, i = idx % CIN;
        s1t[i * 64 + j] = w1[idx];
    }
    for (int idx = tid; idx < COUT * 64; idx += blockDim.x) {
        int c = idx / 64, j = idx % 64;
        s2t[j * COUT + c] = w2[idx];
    }
    __syncthreads();

    int lane   = tid & 31;
    int nwarps = (gridDim.x * blockDim.x) >> 5;
    int w0     = (blockIdx.x * blockDim.x + tid) >> 5;

    for (int n = w0; n < NN; n += nwarps) {
        float h = out[n * COUT + lane];
        float a0 = 0.0f, a1 = 0.0f;   // hidden units lane and lane+32
        #pragma unroll
        for (int i = 0; i < CIN; i++) {
            float hv = __shfl_sync(0xffffffffu, h, i);
            a0 = fmaf(hv, s1t[i * 64 + lane],      a0);
            a1 = fmaf(hv, s1t[i * 64 + 32 + lane], a1);
        }
        a0 = fmaxf(a0, 0.0f);
        a1 = fmaxf(a1, 0.0f);
        float o = h;  // skip connection
        #pragma unroll
        for (int j = 0; j < 32; j++) {
            float v0 = __shfl_sync(0xffffffffu, a0, j);
            float v1 = __shfl_sync(0xffffffffu, a1, j);
            o = fmaf(v0, s2t[j * COUT + lane],        o);
            o = fmaf(v1, s2t[(j + 32) * COUT + lane], o);
        }
        out[n * COUT + lane] = o;
    }
}

extern "C" void kernel_launch(void* const* d_in, const int* in_sizes, int n_in,
                              void* d_out, int out_size) {
    const float* x          = (const float*)d_in[0];
    const float* pos        = (const float*)d_in[1];
    const int*   edge_index = (const int*)  d_in[2];
    const float* ew         = (const float*)d_in[3];
    const float* gw         = (const float*)d_in[4];
    const float* gb         = (const float*)d_in[5];
    const float* w1         = (const float*)d_in[6];
    const float* w2         = (const float*)d_in[7];
    float* out = (float*)d_out;

    init_kernel<<<(NN * COUT / 4 + 255) / 256, 256>>>(out);
    edge_kernel<<<1184, 512>>>(x, pos, edge_index, ew, gw, gb, out);
    mlp_kernel<<<592, 512>>>(w1, w2, out);
}

// round 2
// speedup vs baseline: 2.7703x; 2.7703x over previous
#include <cuda_runtime.h>

#define NN   50000
#define EE   800000
#define CIN  32
#define COUT 32
#define KEXP 4

// Scratch: y[n][k][c] = (x[n] @ W[k])[c], 50000*4*32 floats = 25.6 MB (L2-resident)
__device__ float g_y[NN * KEXP * COUT];

// Order-preserving float atomic max (no empty segments: self-edges guarantee init).
__device__ __forceinline__ void atomicMaxFloat(float* addr, float v) {
    if (v >= 0.0f) atomicMax((int*)addr, __float_as_int(v));
    else           atomicMin((unsigned int*)addr, __float_as_uint(v));
}

__global__ void init_kernel(float* __restrict__ out) {
    int i = blockIdx.x * blockDim.x + threadIdx.x;
    const float NEG_INF = __int_as_float(0xff800000);
    if (i < NN * COUT / 4)
        ((float4*)out)[i] = make_float4(NEG_INF, NEG_INF, NEG_INF, NEG_INF);
}

// Precompute y = x @ W for all K experts. Warp-per-node; weights staged in SMEM
// transposed so one LDS.128 yields all 4 experts' weights for (i, c=lane).
__global__ __launch_bounds__(256) void gemm_kernel(
    const float* __restrict__ x, const float* __restrict__ ew)
{
    __shared__ float4 sWt[CIN * COUT];   // sWt[i*32+c] = {W[0][i][c],W[1][i][c],W[2][i][c],W[3][i][c]}
    int tid = threadIdx.x;
    for (int idx = tid; idx < CIN * COUT; idx += blockDim.x) {
        int i = idx >> 5, c = idx & 31;
        sWt[idx] = make_float4(ew[0 * 1024 + i * 32 + c], ew[1 * 1024 + i * 32 + c],
                               ew[2 * 1024 + i * 32 + c], ew[3 * 1024 + i * 32 + c]);
    }
    __syncthreads();

    int lane  = tid & 31;
    int gwarp = (blockIdx.x * blockDim.x + tid) >> 5;
    int nwarp = (gridDim.x * blockDim.x) >> 5;

    for (int n = gwarp; n < NN; n += nwarp) {
        float xv = x[n * CIN + lane];
        float a0 = 0.f, a1 = 0.f, a2 = 0.f, a3 = 0.f;
        #pragma unroll
        for (int i = 0; i < CIN; i++) {
            float b = __shfl_sync(0xffffffffu, xv, i);
            float4 w = sWt[i * 32 + lane];
            a0 = fmaf(b, w.x, a0); a1 = fmaf(b, w.y, a1);
            a2 = fmaf(b, w.z, a2); a3 = fmaf(b, w.w, a3);
        }
        float* yp = &g_y[n * (KEXP * COUT)];
        yp[lane] = a0; yp[32 + lane] = a1; yp[64 + lane] = a2; yp[96 + lane] = a3;
    }
}

// Edge phase: thread-per-edge gate (lane e), then warp sweeps its 32 edges:
// broadcast offsets via shfl, coalesced 128B gather from y, RED.MAX into out.
__global__ __launch_bounds__(256) void edge_kernel(
    const float* __restrict__ pos, const int* __restrict__ edge_index,
    const float* __restrict__ gw, const float* __restrict__ gb,
    float* __restrict__ out)
{
    float g0x = gw[0], g0y = gw[1], g1x = gw[2], g1y = gw[3];
    float g2x = gw[4], g2y = gw[5], g3x = gw[6], g3y = gw[7];
    float b0 = gb[0], b1 = gb[1], b2 = gb[2], b3 = gb[3];

    int tid   = threadIdx.x;
    int lane  = tid & 31;
    int gwarp = (blockIdx.x * blockDim.x + tid) >> 5;
    int nwarp = (gridDim.x * blockDim.x) >> 5;

    for (int base = gwarp * 32; base < EE; base += nwarp * 32) {
        int e = base + lane;                       // EE % 32 == 0
        int2 ei = ((const int2*)edge_index)[e];
        int dst = ei.x, src = ei.y;

        float dx = pos[src * 3]     - pos[dst * 3];
        float dy = pos[src * 3 + 1] - pos[dst * 3 + 1];

        float l0 = fmaf(dx, g0x, fmaf(dy, g0y, b0));
        float l1 = fmaf(dx, g1x, fmaf(dy, g1y, b1));
        float l2 = fmaf(dx, g2x, fmaf(dy, g2y, b2));
        float l3 = fmaf(dx, g3x, fmaf(dy, g3y, b3));
        int bk = 0; float best = l0;
        if (l1 > best) { best = l1; bk = 1; }
        if (l2 > best) { best = l2; bk = 2; }
        if (l3 > best) { best = l3; bk = 3; }

        int yoff = src * (KEXP * COUT) + bk * COUT;   // per-lane precomputed
        int doff = dst * COUT;

        #pragma unroll
        for (int j = 0; j < 32; j++) {
            int yo = __shfl_sync(0xffffffffu, yoff, j);
            int doo = __shfl_sync(0xffffffffu, doff, j);
            float m = g_y[yo + lane];                 // coalesced 128B, L2 hit
            atomicMaxFloat(&out[doo + lane], m);      // coalesced RED
        }
    }
}

// MLP: thread-per-node, weights broadcast from SMEM as float4 (no shuffles).
__global__ __launch_bounds__(256) void mlp_kernel(
    const float* __restrict__ w1, const float* __restrict__ w2,
    float* __restrict__ out)
{
    __shared__ float4 s1t[CIN * 16];   // s1t[i*16+j4].k = w1[(j4*4+k)*32 + i]
    __shared__ float4 s2t[64 * 8];     // s2t[j*8 +c4].k = w2[(c4*4+k)*64 + j]
    int tid = threadIdx.x;
    for (int idx = tid; idx < CIN * 16; idx += blockDim.x) {
        int i = idx >> 4, j4 = idx & 15;
        s1t[idx] = make_float4(w1[(j4 * 4 + 0) * 32 + i], w1[(j4 * 4 + 1) * 32 + i],
                               w1[(j4 * 4 + 2) * 32 + i], w1[(j4 * 4 + 3) * 32 + i]);
    }
    for (int idx = tid; idx < 64 * 8; idx += blockDim.x) {
        int j = idx >> 3, c4 = idx & 7;
        s2t[idx] = make_float4(w2[(c4 * 4 + 0) * 64 + j], w2[(c4 * 4 + 1) * 64 + j],
                               w2[(c4 * 4 + 2) * 64 + j], w2[(c4 * 4 + 3) * 64 + j]);
    }
    __syncthreads();

    int n = blockIdx.x * blockDim.x + tid;
    if (n >= NN) return;

    float h[CIN];
    #pragma unroll
    for (int i = 0; i < CIN / 4; i++) {
        float4 v = ((const float4*)(out + n * COUT))[i];
        h[i * 4] = v.x; h[i * 4 + 1] = v.y; h[i * 4 + 2] = v.z; h[i * 4 + 3] = v.w;
    }

    float a[64];
    #pragma unroll
    for (int j4 = 0; j4 < 16; j4++) {
        float4 acc = make_float4(0.f, 0.f, 0.f, 0.f);
        #pragma unroll
        for (int i = 0; i < CIN; i++) {
            float4 w = s1t[i * 16 + j4];
            acc.x = fmaf(h[i], w.x, acc.x); acc.y = fmaf(h[i], w.y, acc.y);
            acc.z = fmaf(h[i], w.z, acc.z); acc.w = fmaf(h[i], w.w, acc.w);
        }
        a[j4 * 4]     = fmaxf(acc.x, 0.f);
        a[j4 * 4 + 1] = fmaxf(acc.y, 0.f);
        a[j4 * 4 + 2] = fmaxf(acc.z, 0.f);
        a[j4 * 4 + 3] = fmaxf(acc.w, 0.f);
    }

    #pragma unroll
    for (int c4 = 0; c4 < 8; c4++) {
        float4 acc = make_float4(h[c4 * 4], h[c4 * 4 + 1], h[c4 * 4 + 2], h[c4 * 4 + 3]);
        #pragma unroll
        for (int j = 0; j < 64; j++) {
            float4 w = s2t[j * 8 + c4];
            acc.x = fmaf(a[j], w.x, acc.x); acc.y = fmaf(a[j], w.y, acc.y);
            acc.z = fmaf(a[j], w.z, acc.z); acc.w = fmaf(a[j], w.w, acc.w);
        }
        ((float4*)(out + n * COUT))[c4] = acc;
    }
}

extern "C" void kernel_launch(void* const* d_in, const int* in_sizes, int n_in,
                              void* d_out, int out_size) {
    const float* x          = (const float*)d_in[0];
    const float* pos        = (const float*)d_in[1];
    const int*   edge_index = (const int*)  d_in[2];
    const float* ew         = (const float*)d_in[3];
    const float* gw         = (const float*)d_in[4];
    const float* gb         = (const float*)d_in[5];
    const float* w1         = (const float*)d_in[6];
    const float* w2         = (const float*)d_in[7];
    float* out = (float*)d_out;

    init_kernel<<<(NN * COUT / 4 + 511) / 512, 512>>>(out);
    gemm_kernel<<<592, 256>>>(x, ew);
    edge_kernel<<<3125, 256>>>(pos, edge_index, gw, gb, out);
    mlp_kernel<<<(NN + 255) / 256, 256>>>(w1, w2, out);
}

// round 3
// speedup vs baseline: 3.2938x; 1.1890x over previous
#include <cuda_runtime.h>

#define NN   50000
#define EE   800000
#define CIN  32
#define COUT 32
#define KEXP 4

// Scratch: y[n][k][c] = (x[n] @ W[k])[c], 25.6 MB (fits L2)
__device__ float g_y[NN * KEXP * COUT];

// Monotonic float<->uint mapping: preserves order for atomicMax on u32.
__device__ __forceinline__ unsigned int mapFloat(float f) {
    int b = __float_as_int(f);
    return (unsigned int)(b ^ ((b >> 31) | 0x80000000));
}
__device__ __forceinline__ float unmapFloat(unsigned int u) {
    unsigned int b = (u & 0x80000000u) ? (u ^ 0x80000000u) : ~u;
    return __uint_as_float(b);
}
// map(-inf) = ~0xff800000 = 0x007fffff
#define MAPPED_NEG_INF 0x007fffffu

// Precompute y = x @ W for all 4 experts + initialize out row to mapped -inf.
__global__ __launch_bounds__(256) void gemm_kernel(
    const float* __restrict__ x, const float* __restrict__ ew,
    unsigned int* __restrict__ out)
{
    __shared__ float4 sWt[CIN * COUT];   // sWt[i*32+c] = {W[k][i][c]}_{k=0..3}
    int tid = threadIdx.x;
    for (int idx = tid; idx < CIN * COUT; idx += blockDim.x) {
        int i = idx >> 5, c = idx & 31;
        sWt[idx] = make_float4(ew[0 * 1024 + i * 32 + c], ew[1 * 1024 + i * 32 + c],
                               ew[2 * 1024 + i * 32 + c], ew[3 * 1024 + i * 32 + c]);
    }
    __syncthreads();

    int lane  = tid & 31;
    int gwarp = (blockIdx.x * blockDim.x + tid) >> 5;
    int nwarp = (gridDim.x * blockDim.x) >> 5;

    for (int n = gwarp; n < NN; n += nwarp) {
        float xv = x[n * CIN + lane];
        float a0 = 0.f, a1 = 0.f, a2 = 0.f, a3 = 0.f;
        #pragma unroll
        for (int i = 0; i < CIN; i++) {
            float b = __shfl_sync(0xffffffffu, xv, i);
            float4 w = sWt[i * 32 + lane];
            a0 = fmaf(b, w.x, a0); a1 = fmaf(b, w.y, a1);
            a2 = fmaf(b, w.z, a2); a3 = fmaf(b, w.w, a3);
        }
        float* yp = &g_y[n * (KEXP * COUT)];
        yp[lane] = a0; yp[32 + lane] = a1; yp[64 + lane] = a2; yp[96 + lane] = a3;
        out[n * COUT + lane] = MAPPED_NEG_INF;
    }
}

// Edge phase: lane-per-edge gate, warp sweep: broadcast offsets, coalesced
// gather from y, single unconditional RED.MAX.U32 per element.
__global__ __launch_bounds__(256) void edge_kernel(
    const float* __restrict__ pos, const int* __restrict__ edge_index,
    const float* __restrict__ gw, const float* __restrict__ gb,
    unsigned int* __restrict__ out)
{
    float g0x = gw[0], g0y = gw[1], g1x = gw[2], g1y = gw[3];
    float g2x = gw[4], g2y = gw[5], g3x = gw[6], g3y = gw[7];
    float b0 = gb[0], b1 = gb[1], b2 = gb[2], b3 = gb[3];

    int tid   = threadIdx.x;
    int lane  = tid & 31;
    int gwarp = (blockIdx.x * blockDim.x + tid) >> 5;
    int nwarp = (gridDim.x * blockDim.x) >> 5;

    for (int base = gwarp * 32; base < EE; base += nwarp * 32) {
        int e = base + lane;                       // EE % 32 == 0
        int2 ei = ((const int2*)edge_index)[e];
        int dst = ei.x, src = ei.y;

        float dx = pos[src * 3]     - pos[dst * 3];
        float dy = pos[src * 3 + 1] - pos[dst * 3 + 1];

        float l0 = fmaf(dx, g0x, fmaf(dy, g0y, b0));
        float l1 = fmaf(dx, g1x, fmaf(dy, g1y, b1));
        float l2 = fmaf(dx, g2x, fmaf(dy, g2y, b2));
        float l3 = fmaf(dx, g3x, fmaf(dy, g3y, b3));
        int bk = 0; float best = l0;
        if (l1 > best) { best = l1; bk = 1; }
        if (l2 > best) { best = l2; bk = 2; }
        if (l3 > best) { best = l3; bk = 3; }

        int yoff = src * (KEXP * COUT) + bk * COUT;
        int doff = dst * COUT;

        #pragma unroll
        for (int j = 0; j < 32; j++) {
            int yo  = __shfl_sync(0xffffffffu, yoff, j);
            int doo = __shfl_sync(0xffffffffu, doff, j);
            float m = g_y[yo + lane];              // coalesced 128B, L2 hit
            atomicMax(&out[doo + lane], mapFloat(m));   // single RED, no divergence
        }
    }
}

// MLP: thread-per-node, hidden in chunks of 4 to keep regs low.
// Reads mapped uints from out, unmaps, rewrites floats.
__global__ __launch_bounds__(128) void mlp_kernel(
    const float* __restrict__ w1, const float* __restrict__ w2,
    float* __restrict__ out)
{
    __shared__ float4 s1t[CIN * 16];   // s1t[i*16+j4].k = w1[(j4*4+k)*32 + i]
    __shared__ float4 s2t[64 * 8];     // s2t[j*8 +c4].k = w2[(c4*4+k)*64 + j]
    int tid = threadIdx.x;
    for (int idx = tid; idx < CIN * 16; idx += blockDim.x) {
        int i = idx >> 4, j4 = idx & 15;
        s1t[idx] = make_float4(w1[(j4 * 4 + 0) * 32 + i], w1[(j4 * 4 + 1) * 32 + i],
                               w1[(j4 * 4 + 2) * 32 + i], w1[(j4 * 4 + 3) * 32 + i]);
    }
    for (int idx = tid; idx < 64 * 8; idx += blockDim.x) {
        int j = idx >> 3, c4 = idx & 7;
        s2t[idx] = make_float4(w2[(c4 * 4 + 0) * 64 + j], w2[(c4 * 4 + 1) * 64 + j],
                               w2[(c4 * 4 + 2) * 64 + j], w2[(c4 * 4 + 3) * 64 + j]);
    }
    __syncthreads();

    int n = blockIdx.x * blockDim.x + tid;
    if (n >= NN) return;

    float h[CIN];
    const uint4* inp = (const uint4*)(out + n * COUT);
    #pragma unroll
    for (int i = 0; i < CIN / 4; i++) {
        uint4 v = inp[i];
        h[i * 4]     = unmapFloat(v.x);
        h[i * 4 + 1] = unmapFloat(v.y);
        h[i * 4 + 2] = unmapFloat(v.z);
        h[i * 4 + 3] = unmapFloat(v.w);
    }

    float o[COUT];
    #pragma unroll
    for (int c = 0; c < COUT; c++) o[c] = h[c];   // skip connection

    #pragma unroll
    for (int j4 = 0; j4 < 16; j4++) {
        float4 acc = make_float4(0.f, 0.f, 0.f, 0.f);
        #pragma unroll
        for (int i = 0; i < CIN; i++) {
            float4 w = s1t[i * 16 + j4];
            acc.x = fmaf(h[i], w.x, acc.x); acc.y = fmaf(h[i], w.y, acc.y);
            acc.z = fmaf(h[i], w.z, acc.z); acc.w = fmaf(h[i], w.w, acc.w);
        }
        float a0 = fmaxf(acc.x, 0.f), a1 = fmaxf(acc.y, 0.f);
        float a2 = fmaxf(acc.z, 0.f), a3 = fmaxf(acc.w, 0.f);
        int j = j4 * 4;
        #pragma unroll
        for (int c4 = 0; c4 < 8; c4++) {
            float4 wA = s2t[(j + 0) * 8 + c4];
            float4 wB = s2t[(j + 1) * 8 + c4];
            float4 wC = s2t[(j + 2) * 8 + c4];
            float4 wD = s2t[(j + 3) * 8 + c4];
            o[c4*4+0] = fmaf(a0, wA.x, fmaf(a1, wB.x, fmaf(a2, wC.x, fmaf(a3, wD.x, o[c4*4+0]))));
            o[c4*4+1] = fmaf(a0, wA.y, fmaf(a1, wB.y, fmaf(a2, wC.y, fmaf(a3, wD.y, o[c4*4+1]))));
            o[c4*4+2] = fmaf(a0, wA.z, fmaf(a1, wB.z, fmaf(a2, wC.z, fmaf(a3, wD.z, o[c4*4+2]))));
            o[c4*4+3] = fmaf(a0, wA.w, fmaf(a1, wB.w, fmaf(a2, wC.w, fmaf(a3, wD.w, o[c4*4+3]))));
        }
    }

    float4* op = (float4*)(out + n * COUT);
    #pragma unroll
    for (int c4 = 0; c4 < 8; c4++)
        op[c4] = make_float4(o[c4*4], o[c4*4+1], o[c4*4+2], o[c4*4+3]);
}

extern "C" void kernel_launch(void* const* d_in, const int* in_sizes, int n_in,
                              void* d_out, int out_size) {
    const float* x          = (const float*)d_in[0];
    const float* pos        = (const float*)d_in[1];
    const int*   edge_index = (const int*)  d_in[2];
    const float* ew         = (const float*)d_in[3];
    const float* gw         = (const float*)d_in[4];
    const float* gb         = (const float*)d_in[5];
    const float* w1         = (const float*)d_in[6];
    const float* w2         = (const float*)d_in[7];

    gemm_kernel<<<592, 256>>>(x, ew, (unsigned int*)d_out);
    edge_kernel<<<3125, 256>>>(pos, edge_index, gw, gb, (unsigned int*)d_out);
    mlp_kernel<<<(NN + 127) / 128, 128>>>(w1, w2, (float*)d_out);
}